// round 2
// baseline (speedup 1.0000x reference)
#include <cuda_runtime.h>

#define NN 100000
#define NE 3200000
#define DD 64
#define EPSBN 1e-5f

// ---------------- scratch (no allocations allowed) ----------------
__device__ float g_dinv[NN];
__device__ float g_h[(size_t)NN * DD];    // X @ W result (gather source)
__device__ float g_agg[(size_t)NN * DD];  // aggregation target
__device__ float g_y[(size_t)NN * DD];    // FC output (pre-BN)
__device__ float g_stats[2 * DD];         // col sum / sumsq
__device__ float g_bn[2 * DD];            // scale / shift

// ---------------- degree / dinv ----------------
__global__ void k_deg_init() {
    int i = blockIdx.x * blockDim.x + threadIdx.x;
    if (i < NN) g_dinv[i] = 1.0f;  // self loop
}
__global__ void k_deg_count(const int* __restrict__ dst) {
    int e = blockIdx.x * blockDim.x + threadIdx.x;
    if (e < NE) atomicAdd(&g_dinv[dst[e]], 1.0f);
}
__global__ void k_deg_fin() {
    int i = blockIdx.x * blockDim.x + threadIdx.x;
    if (i < NN) g_dinv[i] = rsqrtf(g_dinv[i]);
}

// ---------------- aggregation ----------------
// self-loop contribution, non-atomic init of agg
__global__ void k_agg_init(const float* __restrict__ h, float* __restrict__ agg) {
    int i = blockIdx.x * blockDim.x + threadIdx.x;
    if (i < NN * DD) {
        int row = i >> 6;
        float di = g_dinv[row];
        agg[i] = di * di * h[i];
    }
}

// 16 threads per edge, one float4 each
__global__ void k_agg_edges(const int* __restrict__ src,
                            const int* __restrict__ dst,
                            const float* __restrict__ h,
                            float* __restrict__ agg) {
    long long gid = (long long)blockIdx.x * blockDim.x + threadIdx.x;
    int e = (int)(gid >> 4);
    int q = (int)(gid & 15);
    if (e >= NE) return;
    int s = src[e];
    int d = dst[e];
    float w = g_dinv[s] * g_dinv[d];
    float4 v = *reinterpret_cast<const float4*>(h + (size_t)s * DD + q * 4);
    float* p = agg + (size_t)d * DD + q * 4;
    atomicAdd(p + 0, w * v.x);
    atomicAdd(p + 1, w * v.y);
    atomicAdd(p + 2, w * v.z);
    atomicAdd(p + 3, w * v.w);
}

// ---------------- GEMM: out[N,64] = f(in)[N,64] @ W[64,64] (+ outBias) ----
// mode 0: raw input
// mode 1: input + inBias[col]           (folds GCNConv bias into FC)
// mode 2: relu(input*g_bn[c]+g_bn[64+c]) (folds BN+ReLU into next GEMM load)
// doStats: accumulate column sum/sumsq of y into g_stats
__global__ void __launch_bounds__(256) k_gemm(const float* __restrict__ in,
                                              const float* __restrict__ W,
                                              const float* __restrict__ inBias,
                                              const float* __restrict__ outBias,
                                              float* __restrict__ out,
                                              int mode, int doStats) {
    __shared__ float Xt[DD * 68];      // transposed tile [k][row], pad 68
    __shared__ float Ws[DD * DD];
    __shared__ float sred[2][4][DD];

    const int col = threadIdx.x;   // 0..63  (output column)
    const int rg  = threadIdx.y;   // 0..3   (row group of 16)
    const int tid = rg * 64 + col;
    const int r0  = blockIdx.x * 64;

    // load W (4096 floats)
    #pragma unroll
    for (int it = 0; it < 4; it++) {
        int fi = (tid + it * 256) * 4;
        *reinterpret_cast<float4*>(&Ws[fi]) =
            *reinterpret_cast<const float4*>(&W[fi]);
    }
    // load X tile, transform, store transposed
    #pragma unroll
    for (int it = 0; it < 4; it++) {
        int fi = (tid + it * 256) * 4;  // flat float index in 64x64 tile
        int r = fi >> 6;
        int c = fi & 63;
        float4 v;
        if (r0 + r < NN)
            v = *reinterpret_cast<const float4*>(&in[(size_t)(r0 + r) * DD + c]);
        else
            v = make_float4(0.f, 0.f, 0.f, 0.f);
        float vv[4] = {v.x, v.y, v.z, v.w};
        #pragma unroll
        for (int j = 0; j < 4; j++) {
            float t = vv[j];
            int cc = c + j;
            if (mode == 1) t += inBias[cc];
            else if (mode == 2) t = fmaxf(t * g_bn[cc] + g_bn[64 + cc], 0.f);
            Xt[cc * 68 + r] = t;
        }
    }
    __syncthreads();

    float acc[16];
    #pragma unroll
    for (int r = 0; r < 16; r++) acc[r] = 0.f;

    #pragma unroll 4
    for (int k = 0; k < DD; k++) {
        float w = Ws[k * DD + col];
        const float4* xp = reinterpret_cast<const float4*>(&Xt[k * 68 + rg * 16]);
        float4 a0 = xp[0], a1 = xp[1], a2 = xp[2], a3 = xp[3];
        acc[0]  += a0.x * w; acc[1]  += a0.y * w; acc[2]  += a0.z * w; acc[3]  += a0.w * w;
        acc[4]  += a1.x * w; acc[5]  += a1.y * w; acc[6]  += a1.z * w; acc[7]  += a1.w * w;
        acc[8]  += a2.x * w; acc[9]  += a2.y * w; acc[10] += a2.z * w; acc[11] += a2.w * w;
        acc[12] += a3.x * w; acc[13] += a3.y * w; acc[14] += a3.z * w; acc[15] += a3.w * w;
    }

    float ob = outBias ? outBias[col] : 0.f;
    float ps = 0.f, pss = 0.f;
    #pragma unroll
    for (int rr = 0; rr < 16; rr++) {
        int grow = r0 + rg * 16 + rr;
        if (grow < NN) {
            float y = acc[rr] + ob;
            out[(size_t)grow * DD + col] = y;
            ps += y;
            pss += y * y;
        }
    }
    if (doStats) {
        sred[0][rg][col] = ps;
        sred[1][rg][col] = pss;
        __syncthreads();
        if (rg == 0) {
            float s  = sred[0][0][col] + sred[0][1][col] + sred[0][2][col] + sred[0][3][col];
            float ss = sred[1][0][col] + sred[1][1][col] + sred[1][2][col] + sred[1][3][col];
            atomicAdd(&g_stats[col], s);
            atomicAdd(&g_stats[64 + col], ss);
        }
    }
}

// ---------------- BN finalize / apply ----------------
__global__ void k_zero_stats() { g_stats[threadIdx.x] = 0.f; }

__global__ void k_bn_fin(const float* __restrict__ g, const float* __restrict__ bt) {
    int c = threadIdx.x;
    float mu  = g_stats[c] * (1.0f / NN);
    float var = g_stats[64 + c] * (1.0f / NN) - mu * mu;
    float sc  = g[c] * rsqrtf(var + EPSBN);
    g_bn[c] = sc;
    g_bn[64 + c] = bt[c] - mu * sc;
}

__global__ void k_bn_relu_out(const float* __restrict__ y, float* __restrict__ out) {
    int i = blockIdx.x * blockDim.x + threadIdx.x;
    if (i < NN * DD) {
        int c = i & 63;
        out[i] = fmaxf(y[i] * g_bn[c] + g_bn[64 + c], 0.f);
    }
}

// ---------------- launch ----------------
extern "C" void kernel_launch(void* const* d_in, const int* in_sizes, int n_in,
                              void* d_out, int out_size) {
    const float* x   = (const float*)d_in[0];
    const int*   src = (const int*)d_in[1];        // edge_index row 0 (int32!)
    const int*   dst = src + NE;                   // edge_index row 1
    const float *W1  = (const float*)d_in[2],  *b1  = (const float*)d_in[3];
    const float *fw1 = (const float*)d_in[4],  *fb1 = (const float*)d_in[5];
    const float *g1  = (const float*)d_in[6],  *bt1 = (const float*)d_in[7];
    const float *W2  = (const float*)d_in[8],  *b2  = (const float*)d_in[9];
    const float *fw2 = (const float*)d_in[10], *fb2 = (const float*)d_in[11];
    const float *g2  = (const float*)d_in[12], *bt2 = (const float*)d_in[13];
    float* out = (float*)d_out;

    float *ph, *pagg, *py;
    cudaGetSymbolAddress((void**)&ph,   g_h);
    cudaGetSymbolAddress((void**)&pagg, g_agg);
    cudaGetSymbolAddress((void**)&py,   g_y);

    const int T = 256;
    const int elemBlocks = (NN * DD + T - 1) / T;
    const int gemmBlocks = (NN + 63) / 64;
    dim3 gB(64, 4);
    long long aggThreads = (long long)NE * 16;
    int aggBlocks = (int)((aggThreads + T - 1) / T);

    // dinv
    k_deg_init<<<(NN + T - 1) / T, T>>>();
    k_deg_count<<<(NE + T - 1) / T, T>>>(dst);
    k_deg_fin<<<(NN + T - 1) / T, T>>>();

    // ---- layer 1 ----
    k_gemm<<<gemmBlocks, gB>>>(x, W1, nullptr, nullptr, ph, 0, 0);     // h = x@W1
    k_agg_init<<<elemBlocks, T>>>(ph, pagg);                            // self loops
    k_agg_edges<<<aggBlocks, T>>>(src, dst, ph, pagg);                  // scatter-add
    k_zero_stats<<<1, 128>>>();
    k_gemm<<<gemmBlocks, gB>>>(pagg, fw1, b1, fb1, py, 1, 1);           // y1=(agg+b1)@fw1+fb1 + stats
    k_bn_fin<<<1, 64>>>(g1, bt1);

    // ---- layer 2 ----
    k_gemm<<<gemmBlocks, gB>>>(py, W2, nullptr, nullptr, ph, 2, 0);     // h2=bnrelu(y1)@W2
    k_agg_init<<<elemBlocks, T>>>(ph, pagg);
    k_agg_edges<<<aggBlocks, T>>>(src, dst, ph, pagg);
    k_zero_stats<<<1, 128>>>();
    k_gemm<<<gemmBlocks, gB>>>(pagg, fw2, b2, fb2, py, 1, 1);           // y2 + stats
    k_bn_fin<<<1, 64>>>(g2, bt2);
    k_bn_relu_out<<<elemBlocks, T>>>(py, out);                          // d_out
}

// round 3
// speedup vs baseline: 2.8177x; 2.8177x over previous
#include <cuda_runtime.h>

#define NN 100000
#define NE 3200000
#define DD 64
#define EPSBN 1e-5f
#define CHUNK 512
#define NCHUNK ((NN + CHUNK - 1) / CHUNK)   // 196

// ---------------- scratch (no allocations allowed) ----------------
__device__ int   g_deg[NN];
__device__ int   g_off[NN + 1];
__device__ int   g_cursor[NN];
__device__ int   g_csum[256];
__device__ int   g_coff[256];
__device__ float g_dinv[NN];
__device__ int2  g_entries[NE];           // {src, weight-bits}
__device__ float g_h[(size_t)NN * DD];
__device__ float g_agg[(size_t)NN * DD];
__device__ float g_y[(size_t)NN * DD];
__device__ float g_stats[2 * DD];
__device__ float g_bn[2 * DD];

// ---------------- CSR build ----------------
__global__ void k_zero_deg() {
    int i = blockIdx.x * blockDim.x + threadIdx.x;
    if (i < NN) g_deg[i] = 0;
}
__global__ void k_hist(const int* __restrict__ dst) {
    int e = blockIdx.x * blockDim.x + threadIdx.x;
    if (e < NE) atomicAdd(&g_deg[dst[e]], 1);
}
__global__ void k_scan1() {
    __shared__ int sh[CHUNK];
    int c = blockIdx.x, t = threadIdx.x;
    int i = c * CHUNK + t;
    int val = (i < NN) ? g_deg[i] : 0;
    sh[t] = val;
    __syncthreads();
    #pragma unroll
    for (int o = 1; o < CHUNK; o <<= 1) {
        int x = (t >= o) ? sh[t - o] : 0;
        __syncthreads();
        sh[t] += x;
        __syncthreads();
    }
    if (i < NN) g_off[i] = sh[t] - val;   // exclusive (chunk-local)
    if (t == CHUNK - 1) g_csum[c] = sh[t];
}
__global__ void k_scan2() {
    __shared__ int sh[256];
    int t = threadIdx.x;
    int val = (t < NCHUNK) ? g_csum[t] : 0;
    sh[t] = val;
    __syncthreads();
    #pragma unroll
    for (int o = 1; o < 256; o <<= 1) {
        int x = (t >= o) ? sh[t - o] : 0;
        __syncthreads();
        sh[t] += x;
        __syncthreads();
    }
    g_coff[t] = sh[t] - val;              // exclusive chunk offsets
}
__global__ void k_scan3() {
    int i = blockIdx.x * blockDim.x + threadIdx.x;
    if (i < NN) {
        int v = g_off[i] + g_coff[i / CHUNK];
        g_off[i] = v;
        g_cursor[i] = v;
        g_dinv[i] = rsqrtf((float)(g_deg[i] + 1));   // +1 self loop
        if (i == 0) g_off[NN] = NE;
    }
}
__global__ void k_scatter(const int* __restrict__ src, const int* __restrict__ dst) {
    int e = blockIdx.x * blockDim.x + threadIdx.x;
    if (e >= NE) return;
    int s = src[e], d = dst[e];
    float w = g_dinv[s] * g_dinv[d];
    int pos = atomicAdd(&g_cursor[d], 1);
    g_entries[pos] = make_int2(s, __float_as_int(w));
}

// ---------------- aggregation: gather over CSR, self loop folded ----------
__global__ void __launch_bounds__(256) k_agg(const float* __restrict__ h,
                                             float* __restrict__ agg) {
    int node = blockIdx.x * 16 + (threadIdx.x >> 4);
    int q = threadIdx.x & 15;
    if (node >= NN) return;
    int beg = g_off[node];
    int end = g_off[node + 1];
    float di = g_dinv[node];
    float ww = di * di;
    float4 a = *reinterpret_cast<const float4*>(h + (size_t)node * DD + q * 4);
    float4 acc = make_float4(ww * a.x, ww * a.y, ww * a.z, ww * a.w);

    int e = beg;
    for (; e + 2 <= end; e += 2) {
        int2 e0 = g_entries[e];
        int2 e1 = g_entries[e + 1];
        float w0 = __int_as_float(e0.y);
        float w1 = __int_as_float(e1.y);
        float4 v0 = *reinterpret_cast<const float4*>(h + (size_t)e0.x * DD + q * 4);
        float4 v1 = *reinterpret_cast<const float4*>(h + (size_t)e1.x * DD + q * 4);
        acc.x += w0 * v0.x + w1 * v1.x;
        acc.y += w0 * v0.y + w1 * v1.y;
        acc.z += w0 * v0.z + w1 * v1.z;
        acc.w += w0 * v0.w + w1 * v1.w;
    }
    if (e < end) {
        int2 e0 = g_entries[e];
        float w0 = __int_as_float(e0.y);
        float4 v0 = *reinterpret_cast<const float4*>(h + (size_t)e0.x * DD + q * 4);
        acc.x += w0 * v0.x;
        acc.y += w0 * v0.y;
        acc.z += w0 * v0.z;
        acc.w += w0 * v0.w;
    }
    *reinterpret_cast<float4*>(agg + (size_t)node * DD + q * 4) = acc;
}

// ---------------- GEMM: out[N,64] = f(in)[N,64] @ W[64,64] (+ outBias) ----
// mode 0: raw input
// mode 1: input + inBias[col]
// mode 2: relu(input*g_bn[c]+g_bn[64+c])
__global__ void __launch_bounds__(256) k_gemm(const float* __restrict__ in,
                                              const float* __restrict__ W,
                                              const float* __restrict__ inBias,
                                              const float* __restrict__ outBias,
                                              float* __restrict__ out,
                                              int mode, int doStats) {
    __shared__ float Xt[DD * 68];
    __shared__ float Ws[DD * DD];
    __shared__ float sred[2][4][DD];

    const int col = threadIdx.x;
    const int rg  = threadIdx.y;
    const int tid = rg * 64 + col;
    const int r0  = blockIdx.x * 64;

    #pragma unroll
    for (int it = 0; it < 4; it++) {
        int fi = (tid + it * 256) * 4;
        *reinterpret_cast<float4*>(&Ws[fi]) =
            *reinterpret_cast<const float4*>(&W[fi]);
    }
    #pragma unroll
    for (int it = 0; it < 4; it++) {
        int fi = (tid + it * 256) * 4;
        int r = fi >> 6;
        int c = fi & 63;
        float4 v;
        if (r0 + r < NN)
            v = *reinterpret_cast<const float4*>(&in[(size_t)(r0 + r) * DD + c]);
        else
            v = make_float4(0.f, 0.f, 0.f, 0.f);
        float vv[4] = {v.x, v.y, v.z, v.w};
        #pragma unroll
        for (int j = 0; j < 4; j++) {
            float t = vv[j];
            int cc = c + j;
            if (mode == 1) t += inBias[cc];
            else if (mode == 2) t = fmaxf(t * g_bn[cc] + g_bn[64 + cc], 0.f);
            Xt[cc * 68 + r] = t;
        }
    }
    __syncthreads();

    float acc[16];
    #pragma unroll
    for (int r = 0; r < 16; r++) acc[r] = 0.f;

    #pragma unroll 4
    for (int k = 0; k < DD; k++) {
        float w = Ws[k * DD + col];
        const float4* xp = reinterpret_cast<const float4*>(&Xt[k * 68 + rg * 16]);
        float4 a0 = xp[0], a1 = xp[1], a2 = xp[2], a3 = xp[3];
        acc[0]  += a0.x * w; acc[1]  += a0.y * w; acc[2]  += a0.z * w; acc[3]  += a0.w * w;
        acc[4]  += a1.x * w; acc[5]  += a1.y * w; acc[6]  += a1.z * w; acc[7]  += a1.w * w;
        acc[8]  += a2.x * w; acc[9]  += a2.y * w; acc[10] += a2.z * w; acc[11] += a2.w * w;
        acc[12] += a3.x * w; acc[13] += a3.y * w; acc[14] += a3.z * w; acc[15] += a3.w * w;
    }

    float ob = outBias ? outBias[col] : 0.f;
    float ps = 0.f, pss = 0.f;
    #pragma unroll
    for (int rr = 0; rr < 16; rr++) {
        int grow = r0 + rg * 16 + rr;
        if (grow < NN) {
            float y = acc[rr] + ob;
            out[(size_t)grow * DD + col] = y;
            ps += y;
            pss += y * y;
        }
    }
    if (doStats) {
        sred[0][rg][col] = ps;
        sred[1][rg][col] = pss;
        __syncthreads();
        if (rg == 0) {
            float s  = sred[0][0][col] + sred[0][1][col] + sred[0][2][col] + sred[0][3][col];
            float ss = sred[1][0][col] + sred[1][1][col] + sred[1][2][col] + sred[1][3][col];
            atomicAdd(&g_stats[col], s);
            atomicAdd(&g_stats[64 + col], ss);
        }
    }
}

// ---------------- BN finalize / apply ----------------
__global__ void k_zero_stats() { g_stats[threadIdx.x] = 0.f; }

__global__ void k_bn_fin(const float* __restrict__ g, const float* __restrict__ bt) {
    int c = threadIdx.x;
    float mu  = g_stats[c] * (1.0f / NN);
    float var = g_stats[64 + c] * (1.0f / NN) - mu * mu;
    float sc  = g[c] * rsqrtf(var + EPSBN);
    g_bn[c] = sc;
    g_bn[64 + c] = bt[c] - mu * sc;
}

__global__ void k_bn_relu_out(const float* __restrict__ y, float* __restrict__ out) {
    int i = blockIdx.x * blockDim.x + threadIdx.x;
    if (i < NN * DD) {
        int c = i & 63;
        out[i] = fmaxf(y[i] * g_bn[c] + g_bn[64 + c], 0.f);
    }
}

// ---------------- launch ----------------
extern "C" void kernel_launch(void* const* d_in, const int* in_sizes, int n_in,
                              void* d_out, int out_size) {
    const float* x   = (const float*)d_in[0];
    const int*   src = (const int*)d_in[1];
    const int*   dst = src + NE;
    const float *W1  = (const float*)d_in[2],  *b1  = (const float*)d_in[3];
    const float *fw1 = (const float*)d_in[4],  *fb1 = (const float*)d_in[5];
    const float *g1  = (const float*)d_in[6],  *bt1 = (const float*)d_in[7];
    const float *W2  = (const float*)d_in[8],  *b2  = (const float*)d_in[9];
    const float *fw2 = (const float*)d_in[10], *fb2 = (const float*)d_in[11];
    const float *g2  = (const float*)d_in[12], *bt2 = (const float*)d_in[13];
    float* out = (float*)d_out;

    float *ph, *pagg, *py;
    cudaGetSymbolAddress((void**)&ph,   g_h);
    cudaGetSymbolAddress((void**)&pagg, g_agg);
    cudaGetSymbolAddress((void**)&py,   g_y);

    const int T = 256;
    const int elemBlocks = (NN * DD + T - 1) / T;
    const int nodeBlocks = (NN + T - 1) / T;
    const int edgeBlocks = (NE + T - 1) / T;
    const int gemmBlocks = (NN + 63) / 64;
    const int aggBlocks  = (NN + 15) / 16;
    dim3 gB(64, 4);

    // ---- CSR build (once; shared by both layers) ----
    k_zero_deg<<<nodeBlocks, T>>>();
    k_hist<<<edgeBlocks, T>>>(dst);
    k_scan1<<<NCHUNK, CHUNK>>>();
    k_scan2<<<1, 256>>>();
    k_scan3<<<nodeBlocks, T>>>();
    k_scatter<<<edgeBlocks, T>>>(src, dst);

    // ---- layer 1 ----
    k_gemm<<<gemmBlocks, gB>>>(x, W1, nullptr, nullptr, ph, 0, 0);   // h = x@W1
    k_agg<<<aggBlocks, T>>>(ph, pagg);                               // Â h (incl. self loop)
    k_zero_stats<<<1, 128>>>();
    k_gemm<<<gemmBlocks, gB>>>(pagg, fw1, b1, fb1, py, 1, 1);        // y1 + stats
    k_bn_fin<<<1, 64>>>(g1, bt1);

    // ---- layer 2 ----
    k_gemm<<<gemmBlocks, gB>>>(py, W2, nullptr, nullptr, ph, 2, 0);  // h2 = bnrelu(y1)@W2
    k_agg<<<aggBlocks, T>>>(ph, pagg);
    k_zero_stats<<<1, 128>>>();
    k_gemm<<<gemmBlocks, gB>>>(pagg, fw2, b2, fb2, py, 1, 1);        // y2 + stats
    k_bn_fin<<<1, 64>>>(g2, bt2);
    k_bn_relu_out<<<elemBlocks, T>>>(py, out);                       // d_out
}

// round 5
// speedup vs baseline: 2.9702x; 1.0541x over previous
#include <cuda_runtime.h>

#define NN 100000
#define NE 3200000
#define DD 64
#define EPSBN 1e-5f
#define CHUNK 512
#define NCHUNK ((NN + CHUNK - 1) / CHUNK)   // 196

// ---------------- scratch (no allocations allowed) ----------------
__device__ int   g_deg[NN];
__device__ int   g_off[NN + 1];
__device__ int   g_cursor[NN];
__device__ int   g_csum[256];
__device__ int   g_coff[256];
__device__ float g_dinv[NN];
__device__ int2  g_entries[NE];           // {src, weight-bits}
__device__ float g_agg[(size_t)NN * DD];
__device__ float g_y[(size_t)NN * DD];
__device__ float g_stats[2 * DD];
__device__ float g_bn[2 * DD];
__device__ float g_wc[DD * DD];           // combined W@fw
__device__ float g_bc[DD];                // combined bias

// ---------------- CSR build ----------------
__global__ void k_zero_deg() {
    int i = blockIdx.x * blockDim.x + threadIdx.x;
    if (i < NN) g_deg[i] = 0;
}
__global__ void k_hist(const int* __restrict__ dst) {
    int e = blockIdx.x * blockDim.x + threadIdx.x;
    if (e < NE) atomicAdd(&g_deg[dst[e]], 1);
}
__global__ void k_scan1() {
    __shared__ int sh[CHUNK];
    int c = blockIdx.x, t = threadIdx.x;
    int i = c * CHUNK + t;
    int val = (i < NN) ? g_deg[i] : 0;
    sh[t] = val;
    __syncthreads();
    #pragma unroll
    for (int o = 1; o < CHUNK; o <<= 1) {
        int x = (t >= o) ? sh[t - o] : 0;
        __syncthreads();
        sh[t] += x;
        __syncthreads();
    }
    if (i < NN) g_off[i] = sh[t] - val;
    if (t == CHUNK - 1) g_csum[c] = sh[t];
}
__global__ void k_scan2() {
    __shared__ int sh[256];
    int t = threadIdx.x;
    int val = (t < NCHUNK) ? g_csum[t] : 0;
    sh[t] = val;
    __syncthreads();
    #pragma unroll
    for (int o = 1; o < 256; o <<= 1) {
        int x = (t >= o) ? sh[t - o] : 0;
        __syncthreads();
        sh[t] += x;
        __syncthreads();
    }
    g_coff[t] = sh[t] - val;
}
__global__ void k_scan3() {
    int i = blockIdx.x * blockDim.x + threadIdx.x;
    if (i < NN) {
        int v = g_off[i] + g_coff[i / CHUNK];
        g_off[i] = v;
        g_cursor[i] = v;
        g_dinv[i] = rsqrtf((float)(g_deg[i] + 1));   // +1 self loop
        if (i == 0) g_off[NN] = NE;
    }
}
__global__ void k_scatter(const int* __restrict__ src, const int* __restrict__ dst) {
    int e = blockIdx.x * blockDim.x + threadIdx.x;
    if (e >= NE) return;
    int s = src[e], d = dst[e];
    float w = g_dinv[s] * g_dinv[d];
    int pos = atomicAdd(&g_cursor[d], 1);
    g_entries[pos] = make_int2(s, __float_as_int(w));
}

// ---------------- weight combine: Wc = W@fw, bc = b@fw + fb ---------------
__global__ void k_combine(const float* __restrict__ W, const float* __restrict__ fw,
                          const float* __restrict__ b, const float* __restrict__ fb) {
    int col = threadIdx.x;          // 0..63
    int rb  = threadIdx.y * 4;      // row base, y in 0..15
    float acc[4] = {0.f, 0.f, 0.f, 0.f};
    for (int k = 0; k < DD; k++) {
        float f = fw[k * DD + col];
        #pragma unroll
        for (int r = 0; r < 4; r++) acc[r] += W[(rb + r) * DD + k] * f;
    }
    #pragma unroll
    for (int r = 0; r < 4; r++) g_wc[(rb + r) * DD + col] = acc[r];
    if (threadIdx.y == 0) {
        float s = fb[col];
        for (int k = 0; k < DD; k++) s += b[k] * fw[k * DD + col];
        g_bc[col] = s;
    }
}

// ---------------- aggregation: gather over CSR, self loop folded ----------
// mode 0: raw rows; mode 2: row -> relu(row*g_bn + g_bn[64..]) on load
__global__ void __launch_bounds__(256) k_agg(const float* __restrict__ h,
                                             float* __restrict__ agg, int mode) {
    int node = blockIdx.x * 16 + (threadIdx.x >> 4);
    int q = threadIdx.x & 15;
    if (node >= NN) return;

    float4 sc = make_float4(1.f, 1.f, 1.f, 1.f);
    float4 sh = make_float4(0.f, 0.f, 0.f, 0.f);
    if (mode == 2) {
        sc = *reinterpret_cast<const float4*>(&g_bn[q * 4]);
        sh = *reinterpret_cast<const float4*>(&g_bn[64 + q * 4]);
    }

    int beg = g_off[node];
    int end = g_off[node + 1];
    float di = g_dinv[node];
    float ww = di * di;

    float4 a = *reinterpret_cast<const float4*>(h + (size_t)node * DD + q * 4);
    if (mode == 2) {
        a.x = fmaxf(a.x * sc.x + sh.x, 0.f);
        a.y = fmaxf(a.y * sc.y + sh.y, 0.f);
        a.z = fmaxf(a.z * sc.z + sh.z, 0.f);
        a.w = fmaxf(a.w * sc.w + sh.w, 0.f);
    }
    float4 acc = make_float4(ww * a.x, ww * a.y, ww * a.z, ww * a.w);

    int e = beg;
    for (; e + 2 <= end; e += 2) {
        int2 e0 = g_entries[e];
        int2 e1 = g_entries[e + 1];
        float w0 = __int_as_float(e0.y);
        float w1 = __int_as_float(e1.y);
        float4 v0 = *reinterpret_cast<const float4*>(h + (size_t)e0.x * DD + q * 4);
        float4 v1 = *reinterpret_cast<const float4*>(h + (size_t)e1.x * DD + q * 4);
        if (mode == 2) {
            v0.x = fmaxf(v0.x * sc.x + sh.x, 0.f);
            v0.y = fmaxf(v0.y * sc.y + sh.y, 0.f);
            v0.z = fmaxf(v0.z * sc.z + sh.z, 0.f);
            v0.w = fmaxf(v0.w * sc.w + sh.w, 0.f);
            v1.x = fmaxf(v1.x * sc.x + sh.x, 0.f);
            v1.y = fmaxf(v1.y * sc.y + sh.y, 0.f);
            v1.z = fmaxf(v1.z * sc.z + sh.z, 0.f);
            v1.w = fmaxf(v1.w * sc.w + sh.w, 0.f);
        }
        acc.x += w0 * v0.x + w1 * v1.x;
        acc.y += w0 * v0.y + w1 * v1.y;
        acc.z += w0 * v0.z + w1 * v1.z;
        acc.w += w0 * v0.w + w1 * v1.w;
    }
    if (e < end) {
        int2 e0 = g_entries[e];
        float w0 = __int_as_float(e0.y);
        float4 v0 = *reinterpret_cast<const float4*>(h + (size_t)e0.x * DD + q * 4);
        if (mode == 2) {
            v0.x = fmaxf(v0.x * sc.x + sh.x, 0.f);
            v0.y = fmaxf(v0.y * sc.y + sh.y, 0.f);
            v0.z = fmaxf(v0.z * sc.z + sh.z, 0.f);
            v0.w = fmaxf(v0.w * sc.w + sh.w, 0.f);
        }
        acc.x += w0 * v0.x;
        acc.y += w0 * v0.y;
        acc.z += w0 * v0.z;
        acc.w += w0 * v0.w;
    }
    *reinterpret_cast<float4*>(agg + (size_t)node * DD + q * 4) = acc;
}

// ---------------- GEMM: out[N,64] = in[N,64] @ g_wc + g_bc, col stats -----
__global__ void __launch_bounds__(256) k_gemm(const float* __restrict__ in,
                                              float* __restrict__ out) {
    __shared__ float Xt[DD * 68];
    __shared__ float Ws[DD * DD];
    __shared__ float sred[2][4][DD];

    const int col = threadIdx.x;
    const int rg  = threadIdx.y;
    const int tid = rg * 64 + col;
    const int r0  = blockIdx.x * 64;

    #pragma unroll
    for (int it = 0; it < 4; it++) {
        int fi = (tid + it * 256) * 4;
        *reinterpret_cast<float4*>(&Ws[fi]) =
            *reinterpret_cast<const float4*>(&g_wc[fi]);
    }
    #pragma unroll
    for (int it = 0; it < 4; it++) {
        int fi = (tid + it * 256) * 4;
        int r = fi >> 6;
        int c = fi & 63;
        float4 v;
        if (r0 + r < NN)
            v = *reinterpret_cast<const float4*>(&in[(size_t)(r0 + r) * DD + c]);
        else
            v = make_float4(0.f, 0.f, 0.f, 0.f);
        Xt[(c + 0) * 68 + r] = v.x;
        Xt[(c + 1) * 68 + r] = v.y;
        Xt[(c + 2) * 68 + r] = v.z;
        Xt[(c + 3) * 68 + r] = v.w;
    }
    __syncthreads();

    float acc[16];
    #pragma unroll
    for (int r = 0; r < 16; r++) acc[r] = 0.f;

    #pragma unroll 4
    for (int k = 0; k < DD; k++) {
        float w = Ws[k * DD + col];
        const float4* xp = reinterpret_cast<const float4*>(&Xt[k * 68 + rg * 16]);
        float4 a0 = xp[0], a1 = xp[1], a2 = xp[2], a3 = xp[3];
        acc[0]  += a0.x * w; acc[1]  += a0.y * w; acc[2]  += a0.z * w; acc[3]  += a0.w * w;
        acc[4]  += a1.x * w; acc[5]  += a1.y * w; acc[6]  += a1.z * w; acc[7]  += a1.w * w;
        acc[8]  += a2.x * w; acc[9]  += a2.y * w; acc[10] += a2.z * w; acc[11] += a2.w * w;
        acc[12] += a3.x * w; acc[13] += a3.y * w; acc[14] += a3.z * w; acc[15] += a3.w * w;
    }

    float ob = g_bc[col];
    float ps = 0.f, pss = 0.f;
    #pragma unroll
    for (int rr = 0; rr < 16; rr++) {
        int grow = r0 + rg * 16 + rr;
        if (grow < NN) {
            float y = acc[rr] + ob;
            out[(size_t)grow * DD + col] = y;
            ps += y;
            pss += y * y;
        }
    }
    sred[0][rg][col] = ps;
    sred[1][rg][col] = pss;
    __syncthreads();
    if (rg == 0) {
        float s  = sred[0][0][col] + sred[0][1][col] + sred[0][2][col] + sred[0][3][col];
        float ss = sred[1][0][col] + sred[1][1][col] + sred[1][2][col] + sred[1][3][col];
        atomicAdd(&g_stats[col], s);
        atomicAdd(&g_stats[64 + col], ss);
    }
}

// ---------------- BN finalize / apply ----------------
__global__ void k_zero_stats() { g_stats[threadIdx.x] = 0.f; }

__global__ void k_bn_fin(const float* __restrict__ g, const float* __restrict__ bt) {
    int c = threadIdx.x;
    float mu  = g_stats[c] * (1.0f / NN);
    float var = g_stats[64 + c] * (1.0f / NN) - mu * mu;
    float sc  = g[c] * rsqrtf(var + EPSBN);
    g_bn[c] = sc;
    g_bn[64 + c] = bt[c] - mu * sc;
}

__global__ void k_bn_relu_out(const float* __restrict__ y, float* __restrict__ out) {
    int i = blockIdx.x * blockDim.x + threadIdx.x;
    if (i < NN * DD) {
        int c = i & 63;
        out[i] = fmaxf(y[i] * g_bn[c] + g_bn[64 + c], 0.f);
    }
}

// ---------------- launch ----------------
extern "C" void kernel_launch(void* const* d_in, const int* in_sizes, int n_in,
                              void* d_out, int out_size) {
    const float* x   = (const float*)d_in[0];
    const int*   src = (const int*)d_in[1];
    const int*   dst = src + NE;
    const float *W1  = (const float*)d_in[2],  *b1  = (const float*)d_in[3];
    const float *fw1 = (const float*)d_in[4],  *fb1 = (const float*)d_in[5];
    const float *g1  = (const float*)d_in[6],  *bt1 = (const float*)d_in[7];
    const float *W2  = (const float*)d_in[8],  *b2  = (const float*)d_in[9];
    const float *fw2 = (const float*)d_in[10], *fb2 = (const float*)d_in[11];
    const float *g2  = (const float*)d_in[12], *bt2 = (const float*)d_in[13];
    float* out = (float*)d_out;

    float *pagg, *py;
    cudaGetSymbolAddress((void**)&pagg, g_agg);
    cudaGetSymbolAddress((void**)&py,   g_y);

    const int T = 256;
    const int elemBlocks = (NN * DD + T - 1) / T;
    const int nodeBlocks = (NN + T - 1) / T;
    const int edgeBlocks = (NE + T - 1) / T;
    const int gemmBlocks = (NN + 63) / 64;
    const int aggBlocks  = (NN + 15) / 16;
    dim3 gB(64, 4);
    dim3 cB(64, 16);

    // ---- CSR build (once; shared by both layers) ----
    k_zero_deg<<<nodeBlocks, T>>>();
    k_hist<<<edgeBlocks, T>>>(dst);
    k_scan1<<<NCHUNK, CHUNK>>>();
    k_scan2<<<1, 256>>>();
    k_scan3<<<nodeBlocks, T>>>();
    k_scatter<<<edgeBlocks, T>>>(src, dst);

    // ---- layer 1:  y1 = (Â x)(W1@fw1) + bc1 ----
    k_combine<<<1, cB>>>(W1, fw1, b1, fb1);
    k_agg<<<aggBlocks, T>>>(x, pagg, 0);
    k_zero_stats<<<1, 128>>>();
    k_gemm<<<gemmBlocks, gB>>>(pagg, py);
    k_bn_fin<<<1, 64>>>(g1, bt1);

    // ---- layer 2:  y2 = (Â bnrelu(y1))(W2@fw2) + bc2 ----
    k_combine<<<1, cB>>>(W2, fw2, b2, fb2);
    k_agg<<<aggBlocks, T>>>(py, pagg, 2);
    k_zero_stats<<<1, 128>>>();
    k_gemm<<<gemmBlocks, gB>>>(pagg, py);
    k_bn_fin<<<1, 64>>>(g2, bt2);
    k_bn_relu_out<<<elemBlocks, T>>>(py, out);
}